// round 1
// baseline (speedup 1.0000x reference)
#include <cuda_runtime.h>

#define NN 30000
#define NE 480000
#define ND 128       // NODE_DIM
#define SPH 480
#define HID 576
#define NIR 224
#define NB 20

// ---------------- scratch (allocation-free: device globals) ----------------
__device__ float g_h[NN * ND];     // silu(x@W1+b1)
__device__ float g_so[NN * HID];   // scalar_out

// ---------------- vectorized L2 reduction ----------------
__device__ __forceinline__ void red4(float* addr, float4 v) {
    asm volatile("red.global.add.v4.f32 [%0], {%1, %2, %3, %4};"
                 :: "l"(addr), "f"(v.x), "f"(v.y), "f"(v.z), "f"(v.w)
                 : "memory");
}

// ---------------- out init: new = x + (scatter adds later) ----------------
__global__ void init_out_kernel(const float* __restrict__ xs,
                                const float* __restrict__ xsph,
                                float* __restrict__ out) {
    const int n1 = NN * ND / 4;          // 960,000 float4
    const int nt = n1 + NN * SPH / 4;    // + 3,600,000 float4
    const float4* a = (const float4*)xs;
    const float4* b = (const float4*)xsph;
    float4* o = (float4*)out;
    for (int i = blockIdx.x * blockDim.x + threadIdx.x; i < nt;
         i += gridDim.x * blockDim.x) {
        o[i] = (i < n1) ? a[i] : b[i - n1];
    }
}

// ---------------- generic K=128 GEMM: C = act(A[Mx128] @ B[128xN] + bias) ----------------
// block: 64 rows x (N/64) col tiles, 256 threads, 4x4 register tiles
template <int N, bool SILU>
__global__ void gemm_k128(const float* __restrict__ A,
                          const float* __restrict__ B,
                          const float* __restrict__ bias,
                          float* __restrict__ C, int M) {
    extern __shared__ float sm[];
    float* As = sm;              // [128][68] A^T (k-major), padded
    float* Bs = sm + 128 * 68;   // [128][64]

    const int row0 = blockIdx.x * 64;
    const int tid = threadIdx.x;

    // load A^T (coalesced on k)
    for (int i = tid; i < 64 * 128; i += 256) {
        int r = i >> 7, k = i & 127;
        float v = (row0 + r < M) ? A[(row0 + r) * ND + k] : 0.f;
        As[k * 68 + r] = v;
    }

    const int tr = tid & 15;   // row quad
    const int tc = tid >> 4;   // col quad

    for (int ct = 0; ct < N / 64; ct++) {
        __syncthreads();   // protects Bs reuse + As first use
        for (int i = tid; i < 128 * 64; i += 256) {
            int k = i >> 6, c = i & 63;
            Bs[k * 64 + c] = B[k * N + ct * 64 + c];
        }
        __syncthreads();

        float acc[4][4] = {};
#pragma unroll 8
        for (int k = 0; k < 128; k++) {
            float4 a = *(const float4*)&As[k * 68 + tr * 4];
            float4 b = *(const float4*)&Bs[k * 64 + tc * 4];
            acc[0][0] = fmaf(a.x, b.x, acc[0][0]);
            acc[0][1] = fmaf(a.x, b.y, acc[0][1]);
            acc[0][2] = fmaf(a.x, b.z, acc[0][2]);
            acc[0][3] = fmaf(a.x, b.w, acc[0][3]);
            acc[1][0] = fmaf(a.y, b.x, acc[1][0]);
            acc[1][1] = fmaf(a.y, b.y, acc[1][1]);
            acc[1][2] = fmaf(a.y, b.z, acc[1][2]);
            acc[1][3] = fmaf(a.y, b.w, acc[1][3]);
            acc[2][0] = fmaf(a.z, b.x, acc[2][0]);
            acc[2][1] = fmaf(a.z, b.y, acc[2][1]);
            acc[2][2] = fmaf(a.z, b.z, acc[2][2]);
            acc[2][3] = fmaf(a.z, b.w, acc[2][3]);
            acc[3][0] = fmaf(a.w, b.x, acc[3][0]);
            acc[3][1] = fmaf(a.w, b.y, acc[3][1]);
            acc[3][2] = fmaf(a.w, b.z, acc[3][2]);
            acc[3][3] = fmaf(a.w, b.w, acc[3][3]);
        }

#pragma unroll
        for (int i = 0; i < 4; i++) {
            int r = row0 + tr * 4 + i;
            if (r < M) {
#pragma unroll
                for (int j = 0; j < 4; j++) {
                    int c = ct * 64 + tc * 4 + j;
                    float v = acc[i][j] + bias[c];
                    if (SILU) v = v / (1.f + __expf(-v));
                    C[r * N + c] = v;
                }
            }
        }
    }
}

// ---------------- edge kernel: filter matvec + gated messages + scatter ----------------
__global__ void __launch_bounds__(192) edge_kernel(
    const float* __restrict__ xsph, const float* __restrict__ rbf,
    const float* __restrict__ fcut, const float* __restrict__ rsh,
    const int* __restrict__ eidx, const float* __restrict__ Wrbf,
    const float* __restrict__ brbf, float* __restrict__ out) {
    const int t = threadIdx.x;

    // per-thread Wrbf slice in registers: columns t, t+192, t+384
    float w[3][NB];
    float bb[3];
#pragma unroll
    for (int j = 0; j < 3; j++) {
        int c = t + 192 * j;
        bb[j] = brbf[c];
#pragma unroll
        for (int b = 0; b < NB; b++) w[j][b] = Wrbf[b * HID + c];
    }

    __shared__ float s_rbf[NB];
    __shared__ float s_fo[HID];
    __shared__ float s_m[SPH];

    float* out_sph = out + NN * ND;

    for (int e = blockIdx.x; e < NE; e += gridDim.x) {
        const int dst = eidx[e];
        const int src = eidx[NE + e];
        if (t < NB) s_rbf[t] = rbf[e * NB + t];
        __syncthreads();
        const float fc = __ldg(&fcut[e]);

        // phase A: fo[c] = scalar_out[src][c] * fcut * (rbf . Wrbf[:,c] + brbf[c])
#pragma unroll
        for (int j = 0; j < 3; j++) {
            int c = t + 192 * j;
            float acc = bb[j];
#pragma unroll
            for (int b = 0; b < NB; b++) acc = fmaf(s_rbf[b], w[j][b], acc);
            s_fo[c] = acc * fc * g_so[src * HID + c];
        }
        __syncthreads();

        // phase B: spherical messages via irrep expansion
#pragma unroll
        for (int rep = 0; rep < 3; rep++) {
            int j = t + 192 * rep;
            if (j < SPH) {
                int ir = (j < 128) ? j
                                   : ((j < 320) ? 128 + (j - 128) / 3
                                                : 192 + (j - 320) / 5);
                s_m[j] = xsph[src * SPH + j] * s_fo[ir] +
                         rsh[e * SPH + j] * s_fo[NIR + ir];
            }
        }
        __syncthreads();

        // phase C: vectorized scatter-add (32 + 120 float4 reds)
        if (t < 32) {
            float4 v = *(const float4*)&s_fo[2 * NIR + t * 4];
            red4(out + dst * ND + t * 4, v);
        } else if (t < 152) {
            int q = t - 32;
            float4 v = *(const float4*)&s_m[q * 4];
            red4(out_sph + dst * SPH + q * 4, v);
        }
        __syncthreads();   // s_fo/s_m must not be overwritten before reds issue
    }
}

// ---------------- launch ----------------
extern "C" void kernel_launch(void* const* d_in, const int* in_sizes, int n_in,
                              void* d_out, int out_size) {
    const float* xs   = (const float*)d_in[0];
    const float* xsph = (const float*)d_in[1];
    const float* rbf  = (const float*)d_in[2];
    const float* fcut = (const float*)d_in[3];
    const float* rsh  = (const float*)d_in[4];
    const int*   eidx = (const int*)d_in[5];
    const float* W1   = (const float*)d_in[6];
    const float* b1   = (const float*)d_in[7];
    const float* W2   = (const float*)d_in[8];
    const float* b2   = (const float*)d_in[9];
    const float* Wrbf = (const float*)d_in[10];
    const float* brbf = (const float*)d_in[11];
    float* out = (float*)d_out;

    float *ph, *pso;
    cudaGetSymbolAddress((void**)&ph, g_h);
    cudaGetSymbolAddress((void**)&pso, g_so);

    const int smem_bytes = (128 * 68 + 128 * 64) * 4;   // 67,584 B
    cudaFuncSetAttribute(gemm_k128<ND, true>,
                         cudaFuncAttributeMaxDynamicSharedMemorySize, smem_bytes);
    cudaFuncSetAttribute(gemm_k128<HID, false>,
                         cudaFuncAttributeMaxDynamicSharedMemorySize, smem_bytes);

    init_out_kernel<<<2048, 256>>>(xs, xsph, out);

    const int gblocks = (NN + 63) / 64;   // 469
    gemm_k128<ND, true><<<gblocks, 256, smem_bytes>>>(xs, W1, b1, ph, NN);
    gemm_k128<HID, false><<<gblocks, 256, smem_bytes>>>(ph, W2, b2, pso, NN);

    edge_kernel<<<444, 192>>>(xsph, rbf, fcut, rsh, eidx, Wrbf, brbf, out);
}